// round 4
// baseline (speedup 1.0000x reference)
#include <cuda_runtime.h>
#include <cuda_bf16.h>

// Problem constants
#define N_CELL 60000
#define N_GENE 4000
#define DIM    128
#define N_EDGE 1500000

// ---------------- device scratch (static allocation only) ----------------
__device__ float g_agg[N_CELL * DIM];   // mean-aggregated gene features per cell (30.7 MB)
__device__ int   g_cnt[N_CELL];         // in-degree per cell
__device__ int   g_off[N_CELL + 1];     // CSR row offsets (by dst)
__device__ int   g_cursor[N_CELL];      // fill cursors
__device__ int   g_esrc[N_EDGE];        // src gene index bucketed by dst cell (6 MB)
__device__ float g_stats[2 * DIM];      // [0:128) col sums, [128:256) col sumsq

// ---------------- kernel 0: zero counters/stats ----------------
__global__ void zero_kernel() {
    int i = blockIdx.x * blockDim.x + threadIdx.x;
    if (i < N_CELL) g_cnt[i] = 0;
    if (i < 2 * DIM) g_stats[i] = 0.0f;
}

// ---------------- kernel 1: histogram of dst ----------------
__global__ void hist_kernel(const int* __restrict__ dst) {
    int i = blockIdx.x * blockDim.x + threadIdx.x;
    if (i < N_EDGE) atomicAdd(&g_cnt[dst[i]], 1);
}

// ---------------- kernel 2: single-block exclusive scan over 60000 bins ----------------
__global__ void scan_kernel() {
    __shared__ int sh[1024];
    const int T = 1024;
    const int per = (N_CELL + T - 1) / T;   // 59
    int t = threadIdx.x;
    int begin = t * per; if (begin > N_CELL) begin = N_CELL;
    int end = begin + per; if (end > N_CELL) end = N_CELL;

    int s = 0;
    for (int i = begin; i < end; i++) s += g_cnt[i];
    sh[t] = s;
    __syncthreads();
    // Hillis-Steele inclusive scan
    for (int off = 1; off < T; off <<= 1) {
        int v = (t >= off) ? sh[t - off] : 0;
        __syncthreads();
        sh[t] += v;
        __syncthreads();
    }
    int run = sh[t] - s;   // exclusive prefix for this chunk
    for (int i = begin; i < end; i++) {
        g_off[i] = run;
        g_cursor[i] = run;
        run += g_cnt[i];
    }
    if (t == T - 1) g_off[N_CELL] = sh[T - 1];
}

// ---------------- kernel 3: bucket fill (CSR by dst) ----------------
__global__ void fill_kernel(const int* __restrict__ src, const int* __restrict__ dst) {
    int i = blockIdx.x * blockDim.x + threadIdx.x;
    if (i < N_EDGE) {
        int p = atomicAdd(&g_cursor[dst[i]], 1);
        g_esrc[p] = src[i];
    }
}

// ---------------- kernel 4: mean aggregation, one warp per cell ----------------
__global__ void agg_kernel(const float* __restrict__ xg) {
    int w = (blockIdx.x * blockDim.x + threadIdx.x) >> 5;
    int lane = threadIdx.x & 31;
    if (w >= N_CELL) return;
    int start = g_off[w];
    int n = g_cnt[w];
    const float4* base = (const float4*)xg;

    float4 acc = make_float4(0.f, 0.f, 0.f, 0.f);
    int i = start, stop = start + n;
    // unroll-by-4 for MLP
    for (; i + 4 <= stop; i += 4) {
        int s0 = __ldg(&g_esrc[i + 0]);
        int s1 = __ldg(&g_esrc[i + 1]);
        int s2 = __ldg(&g_esrc[i + 2]);
        int s3 = __ldg(&g_esrc[i + 3]);
        float4 v0 = __ldg(base + s0 * 32 + lane);
        float4 v1 = __ldg(base + s1 * 32 + lane);
        float4 v2 = __ldg(base + s2 * 32 + lane);
        float4 v3 = __ldg(base + s3 * 32 + lane);
        acc.x += v0.x + v1.x + v2.x + v3.x;
        acc.y += v0.y + v1.y + v2.y + v3.y;
        acc.z += v0.z + v1.z + v2.z + v3.z;
        acc.w += v0.w + v1.w + v2.w + v3.w;
    }
    for (; i < stop; i++) {
        int s = __ldg(&g_esrc[i]);
        float4 v = __ldg(base + s * 32 + lane);
        acc.x += v.x; acc.y += v.y; acc.z += v.z; acc.w += v.w;
    }
    float inv = 1.0f / (float)(n > 0 ? n : 1);
    float4 r = make_float4(acc.x * inv, acc.y * inv, acc.z * inv, acc.w * inv);
    ((float4*)g_agg)[w * 32 + lane] = r;
}

// ---------------- kernel 5: fused GEMM  out = [agg | x_cell] @ [Wl; Wr] + b ----------------
// M=60000, N=128, K=256.  BM=128, BN=128, BK=16, 256 threads, 8x8 per thread,
// packed f32x2 FMA (FFMA2) for 2x fp32 throughput.
__global__ void __launch_bounds__(256, 2)
gemm_kernel(const float* __restrict__ xc,
            const float* __restrict__ wl,   // [128][128] layer-1
            const float* __restrict__ wr,   // [128][128] layer-1
            const float* __restrict__ bias, // [128] layer-1
            float* __restrict__ out) {
    __shared__ unsigned long long As2[128][17]; // A value dup-packed {a,a}, [m][k], pad
    __shared__ float Ws[16][132];               // W tile [k][j], pad

    int row0 = blockIdx.x * 128;
    int tid = threadIdx.x;
    int tx = tid & 15;        // output col group (8 cols)
    int ty = tid >> 4;        // output row group (8 rows)

    unsigned long long acc[8][4] = {}; // 8 rows x 4 col-pairs, bits(0,0)=0.0f,0.0f

    int lm = tid >> 1;             // A-load: row within tile
    int lk = (tid & 1) * 8;        // A-load: k start (0 or 8)
    int lwk = tid >> 4;            // W-load: k row 0..15
    int lwj = (tid & 15) * 8;      // W-load: col start

    for (int k0 = 0; k0 < 256; k0 += 16) {
        // --- load A tile (on-the-fly concat of agg | x_cell), vectorized ---
        float4 av0, av1;
        int gm = row0 + lm;
        if (gm < N_CELL) {
            const float4* src = (const float4*)((k0 < 128)
                ? (g_agg + gm * 128 + k0 + lk)
                : (xc + gm * 128 + (k0 - 128) + lk));
            av0 = __ldg(src);
            av1 = __ldg(src + 1);
        } else {
            av0 = make_float4(0.f, 0.f, 0.f, 0.f);
            av1 = av0;
        }
        {
            float av[8] = {av0.x, av0.y, av0.z, av0.w, av1.x, av1.y, av1.z, av1.w};
            #pragma unroll
            for (int i = 0; i < 8; i++) {
                unsigned long long p;
                asm("mov.b64 %0, {%1, %1};" : "=l"(p) : "f"(av[i]));
                As2[lm][lk + i] = p;
            }
        }
        // --- load W tile, vectorized ---
        {
            const float4* wsrc = (const float4*)((k0 < 128)
                ? (wl + (k0 + lwk) * 128 + lwj)
                : (wr + (k0 - 128 + lwk) * 128 + lwj));
            float4 w0 = __ldg(wsrc);
            float4 w1 = __ldg(wsrc + 1);
            float* dstW = &Ws[lwk][lwj];
            dstW[0] = w0.x; dstW[1] = w0.y; dstW[2] = w0.z; dstW[3] = w0.w;
            dstW[4] = w1.x; dstW[5] = w1.y; dstW[6] = w1.z; dstW[7] = w1.w;
        }
        __syncthreads();

        // --- inner product ---
        #pragma unroll
        for (int kk = 0; kk < 16; kk++) {
            unsigned long long a[8], w[4];
            #pragma unroll
            for (int i = 0; i < 8; i++) a[i] = As2[ty * 8 + i][kk];
            const unsigned long long* wrow =
                (const unsigned long long*)&Ws[kk][tx * 8];
            #pragma unroll
            for (int j = 0; j < 4; j++) w[j] = wrow[j];
            #pragma unroll
            for (int i = 0; i < 8; i++)
                #pragma unroll
                for (int j = 0; j < 4; j++)
                    asm("fma.rn.f32x2 %0, %1, %2, %0;"
                        : "+l"(acc[i][j]) : "l"(a[i]), "l"(w[j]));
        }
        __syncthreads();
    }

    // --- epilogue: add bias, store ---
    float b[8];
    #pragma unroll
    for (int j = 0; j < 8; j++) b[j] = __ldg(&bias[tx * 8 + j]);

    #pragma unroll
    for (int i = 0; i < 8; i++) {
        int gm = row0 + ty * 8 + i;
        if (gm >= N_CELL) continue;
        float v[8];
        #pragma unroll
        for (int j = 0; j < 4; j++) {
            float lo, hi;
            asm("mov.b64 {%0, %1}, %2;" : "=f"(lo), "=f"(hi) : "l"(acc[i][j]));
            v[2 * j] = lo + b[2 * j];
            v[2 * j + 1] = hi + b[2 * j + 1];
        }
        float4* dst = (float4*)(out + gm * 128 + tx * 8);
        dst[0] = make_float4(v[0], v[1], v[2], v[3]);
        dst[1] = make_float4(v[4], v[5], v[6], v[7]);
    }
}

// ---------------- kernel 6: column sums / sumsq ----------------
__global__ void stats_kernel(const float* __restrict__ y) {
    int col = threadIdx.x;            // 128 threads = 128 cols
    int r0 = blockIdx.x * 512;
    int r1 = r0 + 512; if (r1 > N_CELL) r1 = N_CELL;
    float s = 0.f, q = 0.f;
    for (int r = r0; r < r1; r++) {
        float v = __ldg(&y[r * 128 + col]);
        s += v;
        q += v * v;
    }
    atomicAdd(&g_stats[col], s);
    atomicAdd(&g_stats[128 + col], q);
}

// ---------------- kernel 7: batchnorm normalize (in place) ----------------
__global__ void norm_kernel(float* __restrict__ y) {
    __shared__ float mu[128], rs[128];
    if (threadIdx.x < 128) {
        float m = g_stats[threadIdx.x] * (1.0f / N_CELL);
        float var = g_stats[128 + threadIdx.x] * (1.0f / N_CELL) - m * m;
        mu[threadIdx.x] = m;
        rs[threadIdx.x] = rsqrtf(var + 1e-5f);
    }
    __syncthreads();
    const int total = N_CELL * 128 / 4;
    for (int idx = blockIdx.x * blockDim.x + threadIdx.x; idx < total;
         idx += gridDim.x * blockDim.x) {
        float4 v = ((float4*)y)[idx];
        int c = (idx & 31) * 4;
        v.x = (v.x - mu[c + 0]) * rs[c + 0];
        v.y = (v.y - mu[c + 1]) * rs[c + 1];
        v.z = (v.z - mu[c + 2]) * rs[c + 2];
        v.w = (v.w - mu[c + 3]) * rs[c + 3];
        ((float4*)y)[idx] = v;
    }
}

// ---------------- launch ----------------
extern "C" void kernel_launch(void* const* d_in, const int* in_sizes, int n_in,
                              void* d_out, int out_size) {
    const float* x_cell = (const float*)d_in[0];
    const float* x_gene = (const float*)d_in[1];
    // layer 1 (the only live layer): offset past layer 0
    const float* Wl = (const float*)d_in[2] + 128 * 128;
    const float* bl = (const float*)d_in[3] + 128;
    const float* Wr = (const float*)d_in[4] + 128 * 128;
    const int* gc_src = (const int*)d_in[8];
    const int* gc_dst = (const int*)d_in[9];
    float* out = (float*)d_out;

    zero_kernel<<<(N_CELL + 255) / 256, 256>>>();
    hist_kernel<<<(N_EDGE + 255) / 256, 256>>>(gc_dst);
    scan_kernel<<<1, 1024>>>();
    fill_kernel<<<(N_EDGE + 255) / 256, 256>>>(gc_src, gc_dst);
    agg_kernel<<<(N_CELL * 32 + 255) / 256, 256>>>(x_gene);
    gemm_kernel<<<(N_CELL + 127) / 128, 256>>>(x_cell, Wl, Wr, bl, out);
    stats_kernel<<<(N_CELL + 511) / 512, 128>>>(out);
    norm_kernel<<<1024, 256>>>(out);
}

// round 7
// speedup vs baseline: 1.1238x; 1.1238x over previous
#include <cuda_runtime.h>
#include <cuda_bf16.h>

// Problem constants
#define N_CELL 60000
#define N_GENE 4000
#define DIM    128
#define N_EDGE 1500000

// ---------------- device scratch (static allocation only) ----------------
__device__ float g_proj[N_GENE * DIM];  // Y = x_gene @ Wl (2 MB, L2-resident)
__device__ int   g_cnt[N_CELL];         // in-degree per cell
__device__ int   g_off[N_CELL + 1];     // CSR row offsets (by dst)
__device__ int   g_cursor[N_CELL];      // fill cursors
__device__ int   g_esrc[N_EDGE];        // src gene index bucketed by dst cell (6 MB)
__device__ float g_stats[2 * DIM];      // [0:128) col sums, [128:256) col sumsq

// ---------------- kernel 0: zero counters/stats ----------------
__global__ void zero_kernel() {
    int i = blockIdx.x * blockDim.x + threadIdx.x;
    if (i < N_CELL) g_cnt[i] = 0;
    if (i < 2 * DIM) g_stats[i] = 0.0f;
}

// ---------------- kernel 1: histogram of dst ----------------
__global__ void hist_kernel(const int* __restrict__ dst) {
    int i = blockIdx.x * blockDim.x + threadIdx.x;
    if (i < N_EDGE) atomicAdd(&g_cnt[dst[i]], 1);
}

// ---------------- kernel 2: single-block exclusive scan over 60000 bins ----------------
__global__ void scan_kernel() {
    __shared__ int sh[1024];
    const int T = 1024;
    const int per = (N_CELL + T - 1) / T;   // 59
    int t = threadIdx.x;
    int begin = t * per; if (begin > N_CELL) begin = N_CELL;
    int end = begin + per; if (end > N_CELL) end = N_CELL;

    int s = 0;
    for (int i = begin; i < end; i++) s += g_cnt[i];
    sh[t] = s;
    __syncthreads();
    for (int off = 1; off < T; off <<= 1) {
        int v = (t >= off) ? sh[t - off] : 0;
        __syncthreads();
        sh[t] += v;
        __syncthreads();
    }
    int run = sh[t] - s;   // exclusive prefix for this chunk
    for (int i = begin; i < end; i++) {
        g_off[i] = run;
        g_cursor[i] = run;
        run += g_cnt[i];
    }
    if (t == T - 1) g_off[N_CELL] = sh[T - 1];
}

// ---------------- kernel 3: bucket fill (CSR by dst) ----------------
__global__ void fill_kernel(const int* __restrict__ src, const int* __restrict__ dst) {
    int i = blockIdx.x * blockDim.x + threadIdx.x;
    if (i < N_EDGE) {
        int p = atomicAdd(&g_cursor[dst[i]], 1);
        g_esrc[p] = src[i];
    }
}

// ---------------- kernel 4: projection GEMM  Y = x_gene @ Wl  (4000x128x128) ----------
// Same FFMA2 tile structure, M=4000, K=128. Tiny (~0.13 GFLOP).
__global__ void __launch_bounds__(256, 2)
proj_kernel(const float* __restrict__ xg, const float* __restrict__ wl) {
    __shared__ unsigned long long As2[128][17];
    __shared__ float Ws[16][132];

    int row0 = blockIdx.x * 128;
    int tid = threadIdx.x;
    int tx = tid & 15;
    int ty = tid >> 4;

    unsigned long long acc[8][4] = {};

    int lm = tid >> 1;
    int lk = (tid & 1) * 8;
    int lwk = tid >> 4;
    int lwj = (tid & 15) * 8;

    for (int k0 = 0; k0 < 128; k0 += 16) {
        float4 av0, av1;
        int gm = row0 + lm;
        if (gm < N_GENE) {
            const float4* src = (const float4*)(xg + gm * 128 + k0 + lk);
            av0 = __ldg(src);
            av1 = __ldg(src + 1);
        } else {
            av0 = make_float4(0.f, 0.f, 0.f, 0.f);
            av1 = av0;
        }
        {
            float av[8] = {av0.x, av0.y, av0.z, av0.w, av1.x, av1.y, av1.z, av1.w};
            #pragma unroll
            for (int i = 0; i < 8; i++) {
                unsigned long long p;
                asm("mov.b64 %0, {%1, %1};" : "=l"(p) : "f"(av[i]));
                As2[lm][lk + i] = p;
            }
        }
        {
            const float4* wsrc = (const float4*)(wl + (k0 + lwk) * 128 + lwj);
            float4 w0 = __ldg(wsrc);
            float4 w1 = __ldg(wsrc + 1);
            float* dstW = &Ws[lwk][lwj];
            dstW[0] = w0.x; dstW[1] = w0.y; dstW[2] = w0.z; dstW[3] = w0.w;
            dstW[4] = w1.x; dstW[5] = w1.y; dstW[6] = w1.z; dstW[7] = w1.w;
        }
        __syncthreads();

        #pragma unroll
        for (int kk = 0; kk < 16; kk++) {
            unsigned long long a[8], w[4];
            #pragma unroll
            for (int i = 0; i < 8; i++) a[i] = As2[ty * 8 + i][kk];
            const unsigned long long* wrow =
                (const unsigned long long*)&Ws[kk][tx * 8];
            #pragma unroll
            for (int j = 0; j < 4; j++) w[j] = wrow[j];
            #pragma unroll
            for (int i = 0; i < 8; i++)
                #pragma unroll
                for (int j = 0; j < 4; j++)
                    asm("fma.rn.f32x2 %0, %1, %2, %0;"
                        : "+l"(acc[i][j]) : "l"(a[i]), "l"(w[j]));
        }
        __syncthreads();
    }

    #pragma unroll
    for (int i = 0; i < 8; i++) {
        int gm = row0 + ty * 8 + i;
        if (gm >= N_GENE) continue;
        float v[8];
        #pragma unroll
        for (int j = 0; j < 4; j++) {
            float lo, hi;
            asm("mov.b64 {%0, %1}, %2;" : "=f"(lo), "=f"(hi) : "l"(acc[i][j]));
            v[2 * j] = lo;
            v[2 * j + 1] = hi;
        }
        float4* dst = (float4*)(g_proj + gm * 128 + tx * 8);
        dst[0] = make_float4(v[0], v[1], v[2], v[3]);
        dst[1] = make_float4(v[4], v[5], v[6], v[7]);
    }
}

// ---------------- kernel 5: mean aggregation of PROJECTED features -> out ----------
// out[cell] = mean over neighbors of Y[gene]   (left term of the SAGE layer)
__global__ void agg_kernel(float* __restrict__ out) {
    int w = (blockIdx.x * blockDim.x + threadIdx.x) >> 5;
    int lane = threadIdx.x & 31;
    if (w >= N_CELL) return;
    int start = g_off[w];
    int n = g_cnt[w];
    const float4* base = (const float4*)g_proj;

    float4 acc = make_float4(0.f, 0.f, 0.f, 0.f);
    int i = start, stop = start + n;
    for (; i + 4 <= stop; i += 4) {
        int s0 = __ldg(&g_esrc[i + 0]);
        int s1 = __ldg(&g_esrc[i + 1]);
        int s2 = __ldg(&g_esrc[i + 2]);
        int s3 = __ldg(&g_esrc[i + 3]);
        float4 v0 = __ldg(base + s0 * 32 + lane);
        float4 v1 = __ldg(base + s1 * 32 + lane);
        float4 v2 = __ldg(base + s2 * 32 + lane);
        float4 v3 = __ldg(base + s3 * 32 + lane);
        acc.x += v0.x + v1.x + v2.x + v3.x;
        acc.y += v0.y + v1.y + v2.y + v3.y;
        acc.z += v0.z + v1.z + v2.z + v3.z;
        acc.w += v0.w + v1.w + v2.w + v3.w;
    }
    for (; i < stop; i++) {
        int s = __ldg(&g_esrc[i]);
        float4 v = __ldg(base + s * 32 + lane);
        acc.x += v.x; acc.y += v.y; acc.z += v.z; acc.w += v.w;
    }
    float inv = 1.0f / (float)(n > 0 ? n : 1);
    float4 r = make_float4(acc.x * inv, acc.y * inv, acc.z * inv, acc.w * inv);
    ((float4*)out)[w * 32 + lane] = r;
}

// ---------------- kernel 6: GEMM  out += x_cell @ Wr + bl  (K=128) ----------------
__global__ void __launch_bounds__(256, 2)
gemm_kernel(const float* __restrict__ xc,
            const float* __restrict__ wr,   // [128][128] layer-1
            const float* __restrict__ bias, // [128] layer-1
            float* __restrict__ out) {
    __shared__ unsigned long long As2[128][17];
    __shared__ float Ws[16][132];

    int row0 = blockIdx.x * 128;
    int tid = threadIdx.x;
    int tx = tid & 15;
    int ty = tid >> 4;

    unsigned long long acc[8][4] = {};

    int lm = tid >> 1;
    int lk = (tid & 1) * 8;
    int lwk = tid >> 4;
    int lwj = (tid & 15) * 8;

    for (int k0 = 0; k0 < 128; k0 += 16) {
        float4 av0, av1;
        int gm = row0 + lm;
        if (gm < N_CELL) {
            const float4* src = (const float4*)(xc + gm * 128 + k0 + lk);
            av0 = __ldg(src);
            av1 = __ldg(src + 1);
        } else {
            av0 = make_float4(0.f, 0.f, 0.f, 0.f);
            av1 = av0;
        }
        {
            float av[8] = {av0.x, av0.y, av0.z, av0.w, av1.x, av1.y, av1.z, av1.w};
            #pragma unroll
            for (int i = 0; i < 8; i++) {
                unsigned long long p;
                asm("mov.b64 %0, {%1, %1};" : "=l"(p) : "f"(av[i]));
                As2[lm][lk + i] = p;
            }
        }
        {
            const float4* wsrc = (const float4*)(wr + (k0 + lwk) * 128 + lwj);
            float4 w0 = __ldg(wsrc);
            float4 w1 = __ldg(wsrc + 1);
            float* dstW = &Ws[lwk][lwj];
            dstW[0] = w0.x; dstW[1] = w0.y; dstW[2] = w0.z; dstW[3] = w0.w;
            dstW[4] = w1.x; dstW[5] = w1.y; dstW[6] = w1.z; dstW[7] = w1.w;
        }
        __syncthreads();

        #pragma unroll
        for (int kk = 0; kk < 16; kk++) {
            unsigned long long a[8], w[4];
            #pragma unroll
            for (int i = 0; i < 8; i++) a[i] = As2[ty * 8 + i][kk];
            const unsigned long long* wrow =
                (const unsigned long long*)&Ws[kk][tx * 8];
            #pragma unroll
            for (int j = 0; j < 4; j++) w[j] = wrow[j];
            #pragma unroll
            for (int i = 0; i < 8; i++)
                #pragma unroll
                for (int j = 0; j < 4; j++)
                    asm("fma.rn.f32x2 %0, %1, %2, %0;"
                        : "+l"(acc[i][j]) : "l"(a[i]), "l"(w[j]));
        }
        __syncthreads();
    }

    // epilogue: out = preagg(out) + acc + bias
    float b[8];
    #pragma unroll
    for (int j = 0; j < 8; j++) b[j] = __ldg(&bias[tx * 8 + j]);

    #pragma unroll
    for (int i = 0; i < 8; i++) {
        int gm = row0 + ty * 8 + i;
        if (gm >= N_CELL) continue;
        float4* dst = (float4*)(out + gm * 128 + tx * 8);
        float4 p0 = dst[0];
        float4 p1 = dst[1];
        float v[8];
        #pragma unroll
        for (int j = 0; j < 4; j++) {
            float lo, hi;
            asm("mov.b64 {%0, %1}, %2;" : "=f"(lo), "=f"(hi) : "l"(acc[i][j]));
            v[2 * j] = lo + b[2 * j];
            v[2 * j + 1] = hi + b[2 * j + 1];
        }
        dst[0] = make_float4(p0.x + v[0], p0.y + v[1], p0.z + v[2], p0.w + v[3]);
        dst[1] = make_float4(p1.x + v[4], p1.y + v[5], p1.z + v[6], p1.w + v[7]);
    }
}

// ---------------- kernel 7: column sums / sumsq ----------------
__global__ void stats_kernel(const float* __restrict__ y) {
    int col = threadIdx.x;            // 128 threads = 128 cols
    int r0 = blockIdx.x * 512;
    int r1 = r0 + 512; if (r1 > N_CELL) r1 = N_CELL;
    float s = 0.f, q = 0.f;
    for (int r = r0; r < r1; r++) {
        float v = __ldg(&y[r * 128 + col]);
        s += v;
        q += v * v;
    }
    atomicAdd(&g_stats[col], s);
    atomicAdd(&g_stats[128 + col], q);
}

// ---------------- kernel 8: batchnorm normalize (in place) ----------------
__global__ void norm_kernel(float* __restrict__ y) {
    __shared__ float mu[128], rs[128];
    if (threadIdx.x < 128) {
        float m = g_stats[threadIdx.x] * (1.0f / N_CELL);
        float var = g_stats[128 + threadIdx.x] * (1.0f / N_CELL) - m * m;
        mu[threadIdx.x] = m;
        rs[threadIdx.x] = rsqrtf(var + 1e-5f);
    }
    __syncthreads();
    const int total = N_CELL * 128 / 4;
    for (int idx = blockIdx.x * blockDim.x + threadIdx.x; idx < total;
         idx += gridDim.x * blockDim.x) {
        float4 v = ((float4*)y)[idx];
        int c = (idx & 31) * 4;
        v.x = (v.x - mu[c + 0]) * rs[c + 0];
        v.y = (v.y - mu[c + 1]) * rs[c + 1];
        v.z = (v.z - mu[c + 2]) * rs[c + 2];
        v.w = (v.w - mu[c + 3]) * rs[c + 3];
        ((float4*)y)[idx] = v;
    }
}

// ---------------- launch ----------------
extern "C" void kernel_launch(void* const* d_in, const int* in_sizes, int n_in,
                              void* d_out, int out_size) {
    const float* x_cell = (const float*)d_in[0];
    const float* x_gene = (const float*)d_in[1];
    // layer 1 (the only live layer): offset past layer 0
    const float* Wl = (const float*)d_in[2] + 128 * 128;
    const float* bl = (const float*)d_in[3] + 128;
    const float* Wr = (const float*)d_in[4] + 128 * 128;
    const int* gc_src = (const int*)d_in[8];
    const int* gc_dst = (const int*)d_in[9];
    float* out = (float*)d_out;

    zero_kernel<<<(N_CELL + 255) / 256, 256>>>();
    hist_kernel<<<(N_EDGE + 255) / 256, 256>>>(gc_dst);
    scan_kernel<<<1, 1024>>>();
    fill_kernel<<<(N_EDGE + 255) / 256, 256>>>(gc_src, gc_dst);
    proj_kernel<<<(N_GENE + 127) / 128, 256>>>(x_gene, Wl);
    agg_kernel<<<(N_CELL * 32 + 255) / 256, 256>>>(out);
    gemm_kernel<<<(N_CELL + 127) / 128, 256>>>(x_cell, Wr, bl, out);
    stats_kernel<<<(N_CELL + 511) / 512, 128>>>(out);
    norm_kernel<<<1024, 256>>>(out);
}

// round 12
// speedup vs baseline: 1.7043x; 1.5165x over previous
#include <cuda_runtime.h>
#include <cuda_bf16.h>

// Problem constants
#define N_CELL 60000
#define N_GENE 4000
#define DIM    128
#define N_EDGE 1500000
#define SCAN_BLK 256
#define N_SBLK ((N_CELL + SCAN_BLK - 1) / SCAN_BLK)   // 235

// ---------------- device scratch (static allocation only) ----------------
__device__ float g_proj[N_GENE * DIM];  // Y = x_gene @ Wl (2 MB, L2-resident)
__device__ int   g_cnt[N_CELL];         // in-degree per cell
__device__ int   g_off[N_CELL + 1];     // CSR row offsets (by dst)
__device__ int   g_cursor[N_CELL];      // fill cursors
__device__ int   g_esrc[N_EDGE];        // src gene index bucketed by dst cell (6 MB)
__device__ float g_stats[2 * DIM];      // [0:128) col sums, [128:256) col sumsq
__device__ int   g_bsum[N_SBLK];        // per-block count sums
__device__ int   g_bpre[N_SBLK];        // exclusive prefix of block sums

// ---------------- kernel 0: zero counters/stats ----------------
__global__ void zero_kernel() {
    int i = blockIdx.x * blockDim.x + threadIdx.x;
    if (i < N_CELL) g_cnt[i] = 0;
    if (i < 2 * DIM) g_stats[i] = 0.0f;
}

// ---------------- kernel 1: histogram of dst (int4 vectorized) ----------------
__global__ void hist_kernel(const int* __restrict__ dst) {
    int i = blockIdx.x * blockDim.x + threadIdx.x;   // one thread = 4 edges
    if (i < N_EDGE / 4) {
        int4 d = __ldg(((const int4*)dst) + i);
        atomicAdd(&g_cnt[d.x], 1);
        atomicAdd(&g_cnt[d.y], 1);
        atomicAdd(&g_cnt[d.z], 1);
        atomicAdd(&g_cnt[d.w], 1);
    }
}

// ---------------- scan phase A: per-block sums of g_cnt ----------------
__global__ void scan_a_kernel() {
    __shared__ int sh[SCAN_BLK];
    int t = threadIdx.x;
    int i = blockIdx.x * SCAN_BLK + t;
    sh[t] = (i < N_CELL) ? g_cnt[i] : 0;
    __syncthreads();
    for (int off = SCAN_BLK / 2; off > 0; off >>= 1) {
        if (t < off) sh[t] += sh[t + off];
        __syncthreads();
    }
    if (t == 0) g_bsum[blockIdx.x] = sh[0];
}

// ---------------- scan phase B: single-block exclusive scan of 235 block sums ----
__global__ void scan_b_kernel() {
    __shared__ int sh[SCAN_BLK];
    int t = threadIdx.x;
    int v = (t < N_SBLK) ? g_bsum[t] : 0;
    sh[t] = v;
    __syncthreads();
    for (int off = 1; off < SCAN_BLK; off <<= 1) {
        int u = (t >= off) ? sh[t - off] : 0;
        __syncthreads();
        sh[t] += u;
        __syncthreads();
    }
    if (t < N_SBLK) g_bpre[t] = sh[t] - v;   // exclusive
    if (t == SCAN_BLK - 1) g_off[N_CELL] = sh[t];
}

// ---------------- scan phase C: per-block exclusive scan + base -> offsets -----
__global__ void scan_c_kernel() {
    __shared__ int sh[SCAN_BLK];
    int t = threadIdx.x;
    int i = blockIdx.x * SCAN_BLK + t;
    int v = (i < N_CELL) ? g_cnt[i] : 0;
    sh[t] = v;
    __syncthreads();
    for (int off = 1; off < SCAN_BLK; off <<= 1) {
        int u = (t >= off) ? sh[t - off] : 0;
        __syncthreads();
        sh[t] += u;
        __syncthreads();
    }
    if (i < N_CELL) {
        int o = g_bpre[blockIdx.x] + sh[t] - v;   // exclusive prefix
        g_off[i] = o;
        g_cursor[i] = o;
    }
}

// ---------------- kernel 3: bucket fill (CSR by dst) ----------------
__global__ void fill_kernel(const int* __restrict__ src, const int* __restrict__ dst) {
    int i = blockIdx.x * blockDim.x + threadIdx.x;
    if (i < N_EDGE) {
        int p = atomicAdd(&g_cursor[dst[i]], 1);
        g_esrc[p] = src[i];
    }
}

// ---------------- kernel 4: projection GEMM  Y = x_gene @ Wl  (4000x128x128) ----------
__global__ void __launch_bounds__(256, 2)
proj_kernel(const float* __restrict__ xg, const float* __restrict__ wl) {
    __shared__ unsigned long long As2[128][17];
    __shared__ float Ws[16][132];

    int row0 = blockIdx.x * 128;
    int tid = threadIdx.x;
    int tx = tid & 15;
    int ty = tid >> 4;

    unsigned long long acc[8][4] = {};

    int lm = tid >> 1;
    int lk = (tid & 1) * 8;
    int lwk = tid >> 4;
    int lwj = (tid & 15) * 8;

    for (int k0 = 0; k0 < 128; k0 += 16) {
        float4 av0, av1;
        int gm = row0 + lm;
        if (gm < N_GENE) {
            const float4* src = (const float4*)(xg + gm * 128 + k0 + lk);
            av0 = __ldg(src);
            av1 = __ldg(src + 1);
        } else {
            av0 = make_float4(0.f, 0.f, 0.f, 0.f);
            av1 = av0;
        }
        {
            float av[8] = {av0.x, av0.y, av0.z, av0.w, av1.x, av1.y, av1.z, av1.w};
            #pragma unroll
            for (int i = 0; i < 8; i++) {
                unsigned long long p;
                asm("mov.b64 %0, {%1, %1};" : "=l"(p) : "f"(av[i]));
                As2[lm][lk + i] = p;
            }
        }
        {
            const float4* wsrc = (const float4*)(wl + (k0 + lwk) * 128 + lwj);
            float4 w0 = __ldg(wsrc);
            float4 w1 = __ldg(wsrc + 1);
            float* dstW = &Ws[lwk][lwj];
            dstW[0] = w0.x; dstW[1] = w0.y; dstW[2] = w0.z; dstW[3] = w0.w;
            dstW[4] = w1.x; dstW[5] = w1.y; dstW[6] = w1.z; dstW[7] = w1.w;
        }
        __syncthreads();

        #pragma unroll
        for (int kk = 0; kk < 16; kk++) {
            unsigned long long a[8], w[4];
            #pragma unroll
            for (int i = 0; i < 8; i++) a[i] = As2[ty * 8 + i][kk];
            const unsigned long long* wrow =
                (const unsigned long long*)&Ws[kk][tx * 8];
            #pragma unroll
            for (int j = 0; j < 4; j++) w[j] = wrow[j];
            #pragma unroll
            for (int i = 0; i < 8; i++)
                #pragma unroll
                for (int j = 0; j < 4; j++)
                    asm("fma.rn.f32x2 %0, %1, %2, %0;"
                        : "+l"(acc[i][j]) : "l"(a[i]), "l"(w[j]));
        }
        __syncthreads();
    }

    #pragma unroll
    for (int i = 0; i < 8; i++) {
        int gm = row0 + ty * 8 + i;
        if (gm >= N_GENE) continue;
        float v[8];
        #pragma unroll
        for (int j = 0; j < 4; j++) {
            float lo, hi;
            asm("mov.b64 {%0, %1}, %2;" : "=f"(lo), "=f"(hi) : "l"(acc[i][j]));
            v[2 * j] = lo;
            v[2 * j + 1] = hi;
        }
        float4* dst = (float4*)(g_proj + gm * 128 + tx * 8);
        dst[0] = make_float4(v[0], v[1], v[2], v[3]);
        dst[1] = make_float4(v[4], v[5], v[6], v[7]);
    }
}

// ---------------- kernel 5: mean aggregation of PROJECTED features -> out ----------
__global__ void agg_kernel(float* __restrict__ out) {
    int w = (blockIdx.x * blockDim.x + threadIdx.x) >> 5;
    int lane = threadIdx.x & 31;
    if (w >= N_CELL) return;
    int start = g_off[w];
    int n = g_cnt[w];
    const float4* base = (const float4*)g_proj;

    float4 acc = make_float4(0.f, 0.f, 0.f, 0.f);
    int i = start, stop = start + n;
    // unroll-by-8 for MLP
    for (; i + 8 <= stop; i += 8) {
        int s[8];
        #pragma unroll
        for (int u = 0; u < 8; u++) s[u] = __ldg(&g_esrc[i + u]);
        float4 v[8];
        #pragma unroll
        for (int u = 0; u < 8; u++) v[u] = __ldg(base + s[u] * 32 + lane);
        #pragma unroll
        for (int u = 0; u < 8; u++) {
            acc.x += v[u].x; acc.y += v[u].y; acc.z += v[u].z; acc.w += v[u].w;
        }
    }
    for (; i < stop; i++) {
        int s = __ldg(&g_esrc[i]);
        float4 v = __ldg(base + s * 32 + lane);
        acc.x += v.x; acc.y += v.y; acc.z += v.z; acc.w += v.w;
    }
    float inv = 1.0f / (float)(n > 0 ? n : 1);
    float4 r = make_float4(acc.x * inv, acc.y * inv, acc.z * inv, acc.w * inv);
    ((float4*)out)[w * 32 + lane] = r;
}

// ---------------- kernel 6: GEMM  out += x_cell @ Wr + bl, fused column stats ----
__global__ void __launch_bounds__(256, 2)
gemm_kernel(const float* __restrict__ xc,
            const float* __restrict__ wr,   // [128][128] layer-1
            const float* __restrict__ bias, // [128] layer-1
            float* __restrict__ out) {
    __shared__ unsigned long long As2[128][17];
    __shared__ float Ws[16][132];
    __shared__ float ssum[128], ssq[128];

    int row0 = blockIdx.x * 128;
    int tid = threadIdx.x;
    int tx = tid & 15;
    int ty = tid >> 4;

    unsigned long long acc[8][4] = {};

    int lm = tid >> 1;
    int lk = (tid & 1) * 8;
    int lwk = tid >> 4;
    int lwj = (tid & 15) * 8;

    if (tid < 128) { ssum[tid] = 0.0f; ssq[tid] = 0.0f; }

    for (int k0 = 0; k0 < 128; k0 += 16) {
        float4 av0, av1;
        int gm = row0 + lm;
        if (gm < N_CELL) {
            const float4* src = (const float4*)(xc + gm * 128 + k0 + lk);
            av0 = __ldg(src);
            av1 = __ldg(src + 1);
        } else {
            av0 = make_float4(0.f, 0.f, 0.f, 0.f);
            av1 = av0;
        }
        {
            float av[8] = {av0.x, av0.y, av0.z, av0.w, av1.x, av1.y, av1.z, av1.w};
            #pragma unroll
            for (int i = 0; i < 8; i++) {
                unsigned long long p;
                asm("mov.b64 %0, {%1, %1};" : "=l"(p) : "f"(av[i]));
                As2[lm][lk + i] = p;
            }
        }
        {
            const float4* wsrc = (const float4*)(wr + (k0 + lwk) * 128 + lwj);
            float4 w0 = __ldg(wsrc);
            float4 w1 = __ldg(wsrc + 1);
            float* dstW = &Ws[lwk][lwj];
            dstW[0] = w0.x; dstW[1] = w0.y; dstW[2] = w0.z; dstW[3] = w0.w;
            dstW[4] = w1.x; dstW[5] = w1.y; dstW[6] = w1.z; dstW[7] = w1.w;
        }
        __syncthreads();

        #pragma unroll
        for (int kk = 0; kk < 16; kk++) {
            unsigned long long a[8], w[4];
            #pragma unroll
            for (int i = 0; i < 8; i++) a[i] = As2[ty * 8 + i][kk];
            const unsigned long long* wrow =
                (const unsigned long long*)&Ws[kk][tx * 8];
            #pragma unroll
            for (int j = 0; j < 4; j++) w[j] = wrow[j];
            #pragma unroll
            for (int i = 0; i < 8; i++)
                #pragma unroll
                for (int j = 0; j < 4; j++)
                    asm("fma.rn.f32x2 %0, %1, %2, %0;"
                        : "+l"(acc[i][j]) : "l"(a[i]), "l"(w[j]));
        }
        __syncthreads();
    }

    // epilogue: out = preagg(out) + acc + bias; accumulate column stats
    float b[8];
    #pragma unroll
    for (int j = 0; j < 8; j++) b[j] = __ldg(&bias[tx * 8 + j]);

    float lsum[8] = {}, lsq[8] = {};

    #pragma unroll
    for (int i = 0; i < 8; i++) {
        int gm = row0 + ty * 8 + i;
        if (gm >= N_CELL) continue;
        float4* dst = (float4*)(out + gm * 128 + tx * 8);
        float4 p0 = dst[0];
        float4 p1 = dst[1];
        float v[8];
        #pragma unroll
        for (int j = 0; j < 4; j++) {
            float lo, hi;
            asm("mov.b64 {%0, %1}, %2;" : "=f"(lo), "=f"(hi) : "l"(acc[i][j]));
            v[2 * j] = lo + b[2 * j];
            v[2 * j + 1] = hi + b[2 * j + 1];
        }
        v[0] += p0.x; v[1] += p0.y; v[2] += p0.z; v[3] += p0.w;
        v[4] += p1.x; v[5] += p1.y; v[6] += p1.z; v[7] += p1.w;
        dst[0] = make_float4(v[0], v[1], v[2], v[3]);
        dst[1] = make_float4(v[4], v[5], v[6], v[7]);
        #pragma unroll
        for (int j = 0; j < 8; j++) {
            lsum[j] += v[j];
            lsq[j] += v[j] * v[j];
        }
    }

    __syncthreads();   // ssum/ssq init visible
    #pragma unroll
    for (int j = 0; j < 8; j++) {
        atomicAdd(&ssum[tx * 8 + j], lsum[j]);
        atomicAdd(&ssq[tx * 8 + j], lsq[j]);
    }
    __syncthreads();
    if (tid < 128) {
        atomicAdd(&g_stats[tid], ssum[tid]);
        atomicAdd(&g_stats[128 + tid], ssq[tid]);
    }
}

// ---------------- kernel 8: batchnorm normalize (in place) ----------------
__global__ void norm_kernel(float* __restrict__ y) {
    __shared__ float mu[128], rs[128];
    if (threadIdx.x < 128) {
        float m = g_stats[threadIdx.x] * (1.0f / N_CELL);
        float var = g_stats[128 + threadIdx.x] * (1.0f / N_CELL) - m * m;
        mu[threadIdx.x] = m;
        rs[threadIdx.x] = rsqrtf(var + 1e-5f);
    }
    __syncthreads();
    const int total = N_CELL * 128 / 4;
    for (int idx = blockIdx.x * blockDim.x + threadIdx.x; idx < total;
         idx += gridDim.x * blockDim.x) {
        float4 v = ((float4*)y)[idx];
        int c = (idx & 31) * 4;
        v.x = (v.x - mu[c + 0]) * rs[c + 0];
        v.y = (v.y - mu[c + 1]) * rs[c + 1];
        v.z = (v.z - mu[c + 2]) * rs[c + 2];
        v.w = (v.w - mu[c + 3]) * rs[c + 3];
        ((float4*)y)[idx] = v;
    }
}

// ---------------- launch ----------------
extern "C" void kernel_launch(void* const* d_in, const int* in_sizes, int n_in,
                              void* d_out, int out_size) {
    const float* x_cell = (const float*)d_in[0];
    const float* x_gene = (const float*)d_in[1];
    // layer 1 (the only live layer): offset past layer 0
    const float* Wl = (const float*)d_in[2] + 128 * 128;
    const float* bl = (const float*)d_in[3] + 128;
    const float* Wr = (const float*)d_in[4] + 128 * 128;
    const int* gc_src = (const int*)d_in[8];
    const int* gc_dst = (const int*)d_in[9];
    float* out = (float*)d_out;

    zero_kernel<<<(N_CELL + 255) / 256, 256>>>();
    hist_kernel<<<(N_EDGE / 4 + 255) / 256, 256>>>(gc_dst);
    scan_a_kernel<<<N_SBLK, SCAN_BLK>>>();
    scan_b_kernel<<<1, SCAN_BLK>>>();
    scan_c_kernel<<<N_SBLK, SCAN_BLK>>>();
    fill_kernel<<<(N_EDGE + 255) / 256, 256>>>(gc_src, gc_dst);
    proj_kernel<<<(N_GENE + 127) / 128, 256>>>(x_gene, Wl);
    agg_kernel<<<(N_CELL * 32 + 255) / 256, 256>>>(out);
    gemm_kernel<<<(N_CELL + 127) / 128, 256>>>(x_cell, Wr, bl, out);
    norm_kernel<<<1024, 256>>>(out);
}